// round 3
// baseline (speedup 1.0000x reference)
#include <cuda_runtime.h>
#include <cuda_bf16.h>
#include <math.h>
#include <stdint.h>

#define D    128
#define Bn   4
#define NSn  10000
#define NTn  10000
#define En   160000
#define Kc   16
#define LDS_T 136   // padded bf16 row (272B) for conflict-free ldmatrix
#define LDX   136   // padded fp32 row (544B) for conflict-free fragment loads
#define LDC   132
#define TILE_M 128
#define NTILES (Bn * En / TILE_M)   // 5000

// ---------------- scratch ----------------
__device__ float g_Ps  [Bn * NSn * D];
__device__ float g_Pt  [Bn * NTn * D];
__device__ float g_Ptt [Bn * NTn * D];
__device__ float g_db  [Bn * En  * D];
__device__ float g_red [Bn * NTn * D];
__device__ __nv_bfloat16 g_Wh[5 * D * D];   // 0=W_s2e 1=W_t2e 2=W_e2e 3=W_e2t 4=W_t2t
__device__ __nv_bfloat16 g_Wl[5 * D * D];

// ---------------- PTX helpers ----------------
__device__ __forceinline__ uint32_t smem_u32(const void* p) {
    return (uint32_t)__cvta_generic_to_shared(p);
}
__device__ __forceinline__ void ldsm4(uint32_t a, uint32_t& r0, uint32_t& r1, uint32_t& r2, uint32_t& r3) {
    asm volatile("ldmatrix.sync.aligned.m8n8.x4.shared.b16 {%0,%1,%2,%3}, [%4];"
                 : "=r"(r0), "=r"(r1), "=r"(r2), "=r"(r3) : "r"(a));
}
__device__ __forceinline__ void ldsm4t(uint32_t a, uint32_t& r0, uint32_t& r1, uint32_t& r2, uint32_t& r3) {
    asm volatile("ldmatrix.sync.aligned.m8n8.x4.trans.shared.b16 {%0,%1,%2,%3}, [%4];"
                 : "=r"(r0), "=r"(r1), "=r"(r2), "=r"(r3) : "r"(a));
}
__device__ __forceinline__ void mma16816(float c[4], uint32_t a0, uint32_t a1, uint32_t a2, uint32_t a3,
                                         uint32_t b0, uint32_t b1) {
    asm volatile("mma.sync.aligned.m16n8k16.row.col.f32.bf16.bf16.f32 "
                 "{%0,%1,%2,%3},{%4,%5,%6,%7},{%8,%9},{%0,%1,%2,%3};"
                 : "+f"(c[0]), "+f"(c[1]), "+f"(c[2]), "+f"(c[3])
                 : "r"(a0), "r"(a1), "r"(a2), "r"(a3), "r"(b0), "r"(b1));
}
__device__ __forceinline__ void cp16(uint32_t dst, const void* src) {
    asm volatile("cp.async.cg.shared.global [%0], [%1], 16;" :: "r"(dst), "l"(src));
}
__device__ __forceinline__ void cp_commit() { asm volatile("cp.async.commit_group;"); }
__device__ __forceinline__ void cp_wait1()  { asm volatile("cp.async.wait_group 1;"); }

// split a float2 into hi/lo bf16x2 packed regs
__device__ __forceinline__ void split2(float2 v, uint32_t& hi, uint32_t& lo) {
    __nv_bfloat16 hx = __float2bfloat16(v.x), hy = __float2bfloat16(v.y);
    __nv_bfloat162 h; h.x = hx; h.y = hy;
    __nv_bfloat162 l;
    l.x = __float2bfloat16(v.x - __bfloat162float(hx));
    l.y = __float2bfloat16(v.y - __bfloat162float(hy));
    hi = *(uint32_t*)&h;
    lo = *(uint32_t*)&l;
}
__device__ __forceinline__ float silu_f(float x) { return x / (1.0f + __expf(-x)); }

// ---------------- weight pre-split ----------------
__global__ __launch_bounds__(256) void prep_w_kernel(const float* __restrict__ W0,
                                                     const float* __restrict__ W1,
                                                     const float* __restrict__ W2,
                                                     const float* __restrict__ W3,
                                                     const float* __restrict__ W4) {
    int i = blockIdx.x * 256 + threadIdx.x;
    int w = i >> 14, j = i & (D * D - 1);
    const float* W = (w == 0) ? W0 : (w == 1) ? W1 : (w == 2) ? W2 : (w == 3) ? W3 : W4;
    float x = W[j];
    __nv_bfloat16 h = __float2bfloat16(x);
    g_Wh[i] = h;
    g_Wl[i] = __float2bfloat16(x - __bfloat162float(h));
}

// ---------------- small-kernel shared pieces (R2-proven) ----------------
__device__ __forceinline__ void load_W_tile(__nv_bfloat16* Wh, __nv_bfloat16* Wl, int widx, int tid) {
    const __nv_bfloat16* gh = g_Wh + widx * D * D;
    const __nv_bfloat16* gl = g_Wl + widx * D * D;
    #pragma unroll
    for (int i = tid; i < D * 16; i += 256) {
        int r = i >> 4, c = (i & 15) * 8;
        *(uint4*)(Wh + r * LDS_T + c) = *(const uint4*)(gh + r * D + c);
        *(uint4*)(Wl + r * LDS_T + c) = *(const uint4*)(gl + r * D + c);
    }
}
__device__ __forceinline__ void load_X_split(__nv_bfloat16* Xh, __nv_bfloat16* Xl,
                                             const float* __restrict__ Xg, int tid) {
    #pragma unroll
    for (int i = tid; i < 64 * 32; i += 256) {
        int r = i >> 5, c = (i & 31) * 4;
        float4 v = *(const float4*)(Xg + (size_t)r * D + c);
        uint32_t h0, l0, h1, l1;
        split2(make_float2(v.x, v.y), h0, l0);
        split2(make_float2(v.z, v.w), h1, l1);
        *(uint32_t*)(Xh + r * LDS_T + c)     = h0;
        *(uint32_t*)(Xh + r * LDS_T + c + 2) = h1;
        *(uint32_t*)(Xl + r * LDS_T + c)     = l0;
        *(uint32_t*)(Xl + r * LDS_T + c + 2) = l1;
    }
}
__device__ __forceinline__ void gemm_mma64(const __nv_bfloat16* Xh, const __nv_bfloat16* Xl,
                                           const __nv_bfloat16* Wh, const __nv_bfloat16* Wl,
                                           int tid, float acc[8][4]) {
    int lane = tid & 31, w = tid >> 5;
    int rg = (w & 3) * 16, cg = (w >> 2) * 64;
    #pragma unroll
    for (int i = 0; i < 8; i++)
        #pragma unroll
        for (int j = 0; j < 4; j++) acc[i][j] = 0.0f;
    int l7 = lane & 7, lm = lane >> 3;
    int a_row = rg + l7 + ((lm & 1) << 3);
    int a_cad = (lm >> 1) << 3;
    uint32_t aH = smem_u32(Xh + a_row * LDS_T + a_cad);
    uint32_t aL = smem_u32(Xl + a_row * LDS_T + a_cad);
    int b_krow = l7 + ((lm & 1) << 3);
    int b_cad  = (lm >> 1) << 3;
    uint32_t bH[4], bL[4];
    #pragma unroll
    for (int nr = 0; nr < 4; nr++) {
        int col = cg + nr * 16 + b_cad;
        bH[nr] = smem_u32(Wh + b_krow * LDS_T + col);
        bL[nr] = smem_u32(Wl + b_krow * LDS_T + col);
    }
    #pragma unroll
    for (int k0 = 0; k0 < D; k0 += 16) {
        uint32_t ah0, ah1, ah2, ah3, al0, al1, al2, al3;
        ldsm4(aH + k0 * 2, ah0, ah1, ah2, ah3);
        ldsm4(aL + k0 * 2, al0, al1, al2, al3);
        uint32_t koff = (uint32_t)(k0 * LDS_T * 2);
        #pragma unroll
        for (int nr = 0; nr < 4; nr++) {
            uint32_t bh0, bh1, bh2, bh3, bl0, bl1, bl2, bl3;
            ldsm4t(bH[nr] + koff, bh0, bh1, bh2, bh3);
            ldsm4t(bL[nr] + koff, bl0, bl1, bl2, bl3);
            mma16816(acc[2 * nr],     ah0, ah1, ah2, ah3, bh0, bh1);
            mma16816(acc[2 * nr],     ah0, ah1, ah2, ah3, bl0, bl1);
            mma16816(acc[2 * nr],     al0, al1, al2, al3, bh0, bh1);
            mma16816(acc[2 * nr + 1], ah0, ah1, ah2, ah3, bh2, bh3);
            mma16816(acc[2 * nr + 1], ah0, ah1, ah2, ah3, bl2, bl3);
            mma16816(acc[2 * nr + 1], al0, al1, al2, al3, bh2, bh3);
        }
    }
}
__device__ __forceinline__ void stage_acc(float* Cs, const float acc[8][4], int tid) {
    int lane = tid & 31, w = tid >> 5;
    int rg = (w & 3) * 16, cg = (w >> 2) * 64;
    int gid = lane >> 2, tid4 = lane & 3;
    #pragma unroll
    for (int nt = 0; nt < 8; nt++) {
        int col = cg + nt * 8 + tid4 * 2;
        int row = rg + gid;
        *(float2*)(Cs + row * LDC + col)       = make_float2(acc[nt][0], acc[nt][1]);
        *(float2*)(Cs + (row + 8) * LDC + col) = make_float2(acc[nt][2], acc[nt][3]);
    }
}
__device__ __forceinline__ void silu_ln(float v[4], const float gg[4], const float bb[4],
                                        float out[4]) {
    #pragma unroll
    for (int c = 0; c < 4; c++) v[c] = silu_f(v[c]);
    float s1 = v[0] + v[1] + v[2] + v[3];
    float s2 = v[0]*v[0] + v[1]*v[1] + v[2]*v[2] + v[3]*v[3];
    #pragma unroll
    for (int o = 16; o > 0; o >>= 1) {
        s1 += __shfl_xor_sync(0xFFFFFFFFu, s1, o);
        s2 += __shfl_xor_sync(0xFFFFFFFFu, s2, o);
    }
    float m   = s1 * (1.0f / D);
    float var = fmaxf(s2 * (1.0f / D) - m * m, 0.0f);
    float rs  = rsqrtf(var + 1e-5f);
    #pragma unroll
    for (int c = 0; c < 4; c++) out[c] = (v[c] - m) * rs * gg[c] + bb[c];
}

#define SM_SINGLE ((2 * 64 * LDS_T + 2 * D * LDS_T) * 2)
#define SM_DUAL   ((2 * 64 * LDS_T + 4 * D * LDS_T) * 2)

// ---------------- kernel 1: src @ W_s2e -> g_Ps ----------------
__global__ __launch_bounds__(256) void proj_src_kernel(const float* __restrict__ src) {
    extern __shared__ char sm[];
    __nv_bfloat16* Xh = (__nv_bfloat16*)sm;
    __nv_bfloat16* Xl = Xh + 64 * LDS_T;
    __nv_bfloat16* Wh = Xl + 64 * LDS_T;
    __nv_bfloat16* Wl = Wh + D * LDS_T;
    float* Cs = (float*)sm;
    int tid = threadIdx.x;
    int row0 = blockIdx.x * 64;
    load_W_tile(Wh, Wl, 0, tid);
    load_X_split(Xh, Xl, src + (size_t)row0 * D, tid);
    __syncthreads();
    float acc[8][4];
    gemm_mma64(Xh, Xl, Wh, Wl, tid, acc);
    __syncthreads();
    stage_acc(Cs, acc, tid);
    __syncthreads();
    int tx = tid & 31, ty = tid >> 5;
    #pragma unroll
    for (int r = 0; r < 8; r++) {
        float4 v = *(float4*)(Cs + (ty * 8 + r) * LDC + tx * 4);
        *(float4*)(g_Ps + (size_t)(row0 + ty * 8 + r) * D + tx * 4) = v;
    }
}

// ---------------- kernel 2: tgt @ W_t2e -> g_Pt ; tgt @ W_t2t -> g_Ptt ----------------
__global__ __launch_bounds__(256) void proj_tgt_dual_kernel(const float* __restrict__ tgt) {
    extern __shared__ char sm[];
    __nv_bfloat16* Xh  = (__nv_bfloat16*)sm;
    __nv_bfloat16* Xl  = Xh + 64 * LDS_T;
    __nv_bfloat16* Wh1 = Xl + 64 * LDS_T;
    __nv_bfloat16* Wl1 = Wh1 + D * LDS_T;
    __nv_bfloat16* Wh2 = Wl1 + D * LDS_T;
    __nv_bfloat16* Wl2 = Wh2 + D * LDS_T;
    float* Cs = (float*)Wh1;
    int tid = threadIdx.x;
    int row0 = blockIdx.x * 64;
    load_W_tile(Wh1, Wl1, 1, tid);
    load_W_tile(Wh2, Wl2, 4, tid);
    load_X_split(Xh, Xl, tgt + (size_t)row0 * D, tid);
    __syncthreads();
    int tx = tid & 31, ty = tid >> 5;
    {
        float acc[8][4];
        gemm_mma64(Xh, Xl, Wh1, Wl1, tid, acc);
        __syncthreads();
        stage_acc(Cs, acc, tid);
        __syncthreads();
        #pragma unroll
        for (int r = 0; r < 8; r++) {
            float4 v = *(float4*)(Cs + (ty * 8 + r) * LDC + tx * 4);
            *(float4*)(g_Pt + (size_t)(row0 + ty * 8 + r) * D + tx * 4) = v;
        }
        __syncthreads();
    }
    {
        float acc[8][4];
        gemm_mma64(Xh, Xl, Wh2, Wl2, tid, acc);
        __syncthreads();
        stage_acc(Cs, acc, tid);
        __syncthreads();
        #pragma unroll
        for (int r = 0; r < 8; r++) {
            float4 v = *(float4*)(Cs + (ty * 8 + r) * LDC + tx * 4);
            *(float4*)(g_Ptt + (size_t)(row0 + ty * 8 + r) * D + tx * 4) = v;
        }
    }
}

// ================= persistent bond kernel =================
// smem: Xs0, Xs1 (fp32 128x136), Wh, Wl (bf16 128x136), sG, sB (128 fp32 each)
#define SM_BOND (2 * TILE_M * LDX * 4 + 2 * D * LDS_T * 2 + 2 * D * 4)

__global__ __launch_bounds__(256, 1) void bond_kernel(const float* __restrict__ bond,
                                                      const float* __restrict__ g1,
                                                      const float* __restrict__ b1,
                                                      const int* __restrict__ src_order,
                                                      const int* __restrict__ tgt_order,
                                                      float* __restrict__ out0) {
    extern __shared__ char sm[];
    float* Xs0 = (float*)sm;
    float* Xs1 = Xs0 + TILE_M * LDX;
    __nv_bfloat16* Wh = (__nv_bfloat16*)(Xs1 + TILE_M * LDX);
    __nv_bfloat16* Wl = Wh + D * LDS_T;
    float* sG = (float*)(Wl + D * LDS_T);
    float* sB = sG + D;

    int tid = threadIdx.x;
    int lane = tid & 31, w = tid >> 5;
    int rg = w * 16;
    int G = gridDim.x;

    // persistent weight + ln params
    load_W_tile(Wh, Wl, 2, tid);
    if (tid < D) { sG[tid] = g1[tid]; sB[tid] = b1[tid]; }
    __syncthreads();

    int n = (NTILES - blockIdx.x + G - 1) / G;    // tiles for this block

    // prologue: prefetch tiles 0,1
    {
        float* bufs[2] = {Xs0, Xs1};
        #pragma unroll
        for (int p = 0; p < 2; p++) {
            if (p < n) {
                size_t row0 = (size_t)(blockIdx.x + p * G) * TILE_M;
                uint32_t dst = smem_u32(bufs[p]);
                const float* srcp = bond + row0 * D;
                #pragma unroll
                for (int c = tid; c < TILE_M * 32; c += 256) {
                    int r = c >> 5, s = c & 31;
                    cp16(dst + (uint32_t)(r * LDX + s * 4) * 4, srcp + r * D + s * 4);
                }
            }
            cp_commit();
        }
    }

    // fragment base addrs (B operand from persistent W smem)
    int l7 = lane & 7, lm = lane >> 3;
    int b_krow = l7 + ((lm & 1) << 3);
    int b_cad  = (lm >> 1) << 3;
    uint32_t bH[8], bL[8];
    #pragma unroll
    for (int nbp = 0; nbp < 8; nbp++) {
        int col = nbp * 16 + b_cad;
        bH[nbp] = smem_u32(Wh + b_krow * LDS_T + col);
        bL[nbp] = smem_u32(Wl + b_krow * LDS_T + col);
    }
    int g = lane >> 2, t2 = (lane & 3) * 2;
    int rA = rg + g, rB = rg + g + 8;

    for (int i = 0; i < n; i++) {
        cp_wait1();
        __syncthreads();
        float* Xs = (i & 1) ? Xs1 : Xs0;

        float acc[16][4];
        #pragma unroll
        for (int a = 0; a < 16; a++)
            #pragma unroll
            for (int j = 0; j < 4; j++) acc[a][j] = 0.0f;

        #pragma unroll
        for (int k0 = 0; k0 < D; k0 += 16) {
            // build A hi/lo fragments from fp32 smem
            float2 xa = *(float2*)(Xs + rA * LDX + k0 + t2);
            float2 xb = *(float2*)(Xs + rB * LDX + k0 + t2);
            float2 xc = *(float2*)(Xs + rA * LDX + k0 + t2 + 8);
            float2 xd = *(float2*)(Xs + rB * LDX + k0 + t2 + 8);
            uint32_t ah0, al0, ah1, al1, ah2, al2, ah3, al3;
            split2(xa, ah0, al0);
            split2(xb, ah1, al1);
            split2(xc, ah2, al2);
            split2(xd, ah3, al3);
            uint32_t koff = (uint32_t)(k0 * LDS_T * 2);
            #pragma unroll
            for (int nbp = 0; nbp < 8; nbp++) {
                uint32_t bh0, bh1, bh2, bh3, bl0, bl1, bl2, bl3;
                ldsm4t(bH[nbp] + koff, bh0, bh1, bh2, bh3);
                ldsm4t(bL[nbp] + koff, bl0, bl1, bl2, bl3);
                mma16816(acc[2 * nbp],     ah0, ah1, ah2, ah3, bh0, bh1);
                mma16816(acc[2 * nbp],     ah0, ah1, ah2, ah3, bl0, bl1);
                mma16816(acc[2 * nbp],     al0, al1, al2, al3, bh0, bh1);
                mma16816(acc[2 * nbp + 1], ah0, ah1, ah2, ah3, bh2, bh3);
                mma16816(acc[2 * nbp + 1], ah0, ah1, ah2, ah3, bl2, bl3);
                mma16816(acc[2 * nbp + 1], al0, al1, al2, al3, bh2, bh3);
            }
        }

        // ---------- epilogue (rows rA and rB fully owned by this quarter-warp) ----------
        size_t row0 = (size_t)(blockIdx.x + i * G) * TILE_M;
        int b = (int)(row0 / En);
        int ebase = (int)(row0 - (size_t)b * En);

        int soA = src_order[ebase + rA], toA = tgt_order[ebase + rA];
        int soB = src_order[ebase + rB], toB = tgt_order[ebase + rB];
        const float* psA = g_Ps + ((size_t)b * NSn + soA) * D;
        const float* ptA = g_Pt + ((size_t)b * NTn + toA) * D;
        const float* psB = g_Ps + ((size_t)b * NSn + soB) * D;
        const float* ptB = g_Pt + ((size_t)b * NTn + toB) * D;

        float s1A = 0.f, s2A = 0.f, s1B = 0.f, s2B = 0.f;
        #pragma unroll
        for (int nbp = 0; nbp < 8; nbp++) {
            int c0 = nbp * 16 + t2, c1 = c0 + 8;
            float2 pA0 = *(const float2*)(psA + c0), qA0 = *(const float2*)(ptA + c0);
            float2 pA1 = *(const float2*)(psA + c1), qA1 = *(const float2*)(ptA + c1);
            float2 pB0 = *(const float2*)(psB + c0), qB0 = *(const float2*)(ptB + c0);
            float2 pB1 = *(const float2*)(psB + c1), qB1 = *(const float2*)(ptB + c1);
            float v;
            v = silu_f(acc[2*nbp][0]   + pA0.x + qA0.x); acc[2*nbp][0]   = v; s1A += v; s2A += v*v;
            v = silu_f(acc[2*nbp][1]   + pA0.y + qA0.y); acc[2*nbp][1]   = v; s1A += v; s2A += v*v;
            v = silu_f(acc[2*nbp+1][0] + pA1.x + qA1.x); acc[2*nbp+1][0] = v; s1A += v; s2A += v*v;
            v = silu_f(acc[2*nbp+1][1] + pA1.y + qA1.y); acc[2*nbp+1][1] = v; s1A += v; s2A += v*v;
            v = silu_f(acc[2*nbp][2]   + pB0.x + qB0.x); acc[2*nbp][2]   = v; s1B += v; s2B += v*v;
            v = silu_f(acc[2*nbp][3]   + pB0.y + qB0.y); acc[2*nbp][3]   = v; s1B += v; s2B += v*v;
            v = silu_f(acc[2*nbp+1][2] + pB1.x + qB1.x); acc[2*nbp+1][2] = v; s1B += v; s2B += v*v;
            v = silu_f(acc[2*nbp+1][3] + pB1.y + qB1.y); acc[2*nbp+1][3] = v; s1B += v; s2B += v*v;
        }
        #pragma unroll
        for (int o = 2; o > 0; o >>= 1) {
            s1A += __shfl_xor_sync(0xFFFFFFFFu, s1A, o);
            s2A += __shfl_xor_sync(0xFFFFFFFFu, s2A, o);
            s1B += __shfl_xor_sync(0xFFFFFFFFu, s1B, o);
            s2B += __shfl_xor_sync(0xFFFFFFFFu, s2B, o);
        }
        float mA = s1A * (1.0f / D);
        float rsA = rsqrtf(fmaxf(s2A * (1.0f / D) - mA * mA, 0.0f) + 1e-5f);
        float mB = s1B * (1.0f / D);
        float rsB = rsqrtf(fmaxf(s2B * (1.0f / D) - mB * mB, 0.0f) + 1e-5f);

        float* dbA = g_db + (row0 + rA) * D;
        float* dbB = g_db + (row0 + rB) * D;
        float* o0A = out0 + (row0 + rA) * D;
        float* o0B = out0 + (row0 + rB) * D;
        #pragma unroll
        for (int nbp = 0; nbp < 8; nbp++) {
            int c0 = nbp * 16 + t2, c1 = c0 + 8;
            float2 gg0 = *(float2*)(sG + c0), bb0 = *(float2*)(sB + c0);
            float2 gg1 = *(float2*)(sG + c1), bb1 = *(float2*)(sB + c1);
            float2 xA0 = *(float2*)(Xs + rA * LDX + c0);
            float2 xA1 = *(float2*)(Xs + rA * LDX + c1);
            float2 xB0 = *(float2*)(Xs + rB * LDX + c0);
            float2 xB1 = *(float2*)(Xs + rB * LDX + c1);
            float2 d;
            d.x = (acc[2*nbp][0]   - mA) * rsA * gg0.x + bb0.x;
            d.y = (acc[2*nbp][1]   - mA) * rsA * gg0.y + bb0.y;
            *(float2*)(dbA + c0) = d;
            *(float2*)(o0A + c0) = make_float2(xA0.x + d.x, xA0.y + d.y);
            d.x = (acc[2*nbp+1][0] - mA) * rsA * gg1.x + bb1.x;
            d.y = (acc[2*nbp+1][1] - mA) * rsA * gg1.y + bb1.y;
            *(float2*)(dbA + c1) = d;
            *(float2*)(o0A + c1) = make_float2(xA1.x + d.x, xA1.y + d.y);
            d.x = (acc[2*nbp][2]   - mB) * rsB * gg0.x + bb0.x;
            d.y = (acc[2*nbp][3]   - mB) * rsB * gg0.y + bb0.y;
            *(float2*)(dbB + c0) = d;
            *(float2*)(o0B + c0) = make_float2(xB0.x + d.x, xB0.y + d.y);
            d.x = (acc[2*nbp+1][2] - mB) * rsB * gg1.x + bb1.x;
            d.y = (acc[2*nbp+1][3] - mB) * rsB * gg1.y + bb1.y;
            *(float2*)(dbB + c1) = d;
            *(float2*)(o0B + c1) = make_float2(xB1.x + d.x, xB1.y + d.y);
        }

        __syncthreads();
        // prefetch tile i+2 into the buffer we just finished reading
        if (i + 2 < n) {
            size_t prow0 = (size_t)(blockIdx.x + (size_t)(i + 2) * G) * TILE_M;
            uint32_t dst = smem_u32(Xs);
            const float* srcp = bond + prow0 * D;
            #pragma unroll
            for (int c = tid; c < TILE_M * 32; c += 256) {
                int r = c >> 5, s = c & 31;
                cp16(dst + (uint32_t)(r * LDX + s * 4) * 4, srcp + r * D + s * 4);
            }
        }
        cp_commit();
    }
}

// ---------------- kernel 4: bond_reduce ----------------
__global__ __launch_bounds__(256) void reduce_kernel(const int* __restrict__ edge_order,
                                                     const float* __restrict__ coef) {
    int tid  = threadIdx.x;
    int lane = tid & 31;
    int node = (blockIdx.x * blockDim.x + tid) >> 5;
    int b = node / NTn;
    int t = node - b * NTn;
    int   e_l = 0;
    float c_l = 0.0f;
    if (lane < Kc) {
        e_l = edge_order[t * Kc + lane];
        c_l = coef[t * Kc + lane];
    }
    float4 acc = {0.f, 0.f, 0.f, 0.f};
    #pragma unroll
    for (int k = 0; k < Kc; k++) {
        int   e = __shfl_sync(0xFFFFFFFFu, e_l, k);
        float c = __shfl_sync(0xFFFFFFFFu, c_l, k);
        float4 v = *(const float4*)(g_db + ((size_t)b * En + e) * D + lane * 4);
        acc.x += c * v.x;
        acc.y += c * v.y;
        acc.z += c * v.z;
        acc.w += c * v.w;
    }
    const float inv = 1.0f / Kc;
    acc.x *= inv; acc.y *= inv; acc.z *= inv; acc.w *= inv;
    *(float4*)(g_red + (size_t)node * D + lane * 4) = acc;
}

// ---------------- kernel 5: d_tgt ----------------
__global__ __launch_bounds__(256) void tgt_kernel(const float* __restrict__ tgt,
                                                  const float* __restrict__ g2,
                                                  const float* __restrict__ b2,
                                                  float* __restrict__ out2) {
    extern __shared__ char sm[];
    __nv_bfloat16* Xh = (__nv_bfloat16*)sm;
    __nv_bfloat16* Xl = Xh + 64 * LDS_T;
    __nv_bfloat16* Wh = Xl + 64 * LDS_T;
    __nv_bfloat16* Wl = Wh + D * LDS_T;
    float* Cs = (float*)sm;
    int tid = threadIdx.x;
    int row0 = blockIdx.x * 64;
    load_W_tile(Wh, Wl, 3, tid);
    load_X_split(Xh, Xl, g_red + (size_t)row0 * D, tid);
    __syncthreads();
    float acc[8][4];
    gemm_mma64(Xh, Xl, Wh, Wl, tid, acc);
    __syncthreads();
    stage_acc(Cs, acc, tid);
    __syncthreads();

    int tx = tid & 31, ty = tid >> 5;
    float gg[4], bb[4];
    #pragma unroll
    for (int c = 0; c < 4; c++) { gg[c] = g2[tx * 4 + c]; bb[c] = b2[tx * 4 + c]; }
    #pragma unroll
    for (int r = 0; r < 8; r++) {
        int row = row0 + ty * 8 + r;
        float4 cv = *(float4*)(Cs + (ty * 8 + r) * LDC + tx * 4);
        float4 pt = *(const float4*)(g_Ptt + (size_t)row * D + tx * 4);
        float v[4];
        v[0] = cv.x + pt.x;
        v[1] = cv.y + pt.y;
        v[2] = cv.z + pt.z;
        v[3] = cv.w + pt.w;
        float d[4];
        silu_ln(v, gg, bb, d);
        float4 tin = *(const float4*)(tgt + (size_t)row * D + tx * 4);
        float4 o2 = {tin.x + d[0], tin.y + d[1], tin.z + d[2], tin.w + d[3]};
        *(float4*)(out2 + (size_t)row * D + tx * 4) = o2;
    }
}

// ---------------- launch ----------------
extern "C" void kernel_launch(void* const* d_in, const int* in_sizes, int n_in,
                              void* d_out, int out_size) {
    const float* bond  = (const float*)d_in[0];
    const float* src   = (const float*)d_in[1];
    const float* tgt   = (const float*)d_in[2];
    const float* W_s2e = (const float*)d_in[3];
    const float* W_t2e = (const float*)d_in[4];
    const float* W_e2e = (const float*)d_in[5];
    const float* ln1_g = (const float*)d_in[6];
    const float* ln1_b = (const float*)d_in[7];
    const float* W_e2t = (const float*)d_in[8];
    const float* W_t2t = (const float*)d_in[9];
    const float* ln2_g = (const float*)d_in[10];
    const float* ln2_b = (const float*)d_in[11];
    const float* coef  = (const float*)d_in[12];
    const int*   so    = (const int*)d_in[13];
    const int*   to    = (const int*)d_in[14];
    const int*   eo    = (const int*)d_in[15];

    float* out  = (float*)d_out;
    float* out0 = out;
    float* out1 = out0 + (size_t)Bn * En * D;
    float* out2 = out1 + (size_t)Bn * NSn * D;

    int nsm = 148;
    cudaDeviceGetAttribute(&nsm, cudaDevAttrMultiProcessorCount, 0);

    cudaFuncSetAttribute(proj_src_kernel,      cudaFuncAttributeMaxDynamicSharedMemorySize, SM_SINGLE);
    cudaFuncSetAttribute(proj_tgt_dual_kernel, cudaFuncAttributeMaxDynamicSharedMemorySize, SM_DUAL);
    cudaFuncSetAttribute(bond_kernel,          cudaFuncAttributeMaxDynamicSharedMemorySize, SM_BOND);
    cudaFuncSetAttribute(tgt_kernel,           cudaFuncAttributeMaxDynamicSharedMemorySize, SM_SINGLE);

    prep_w_kernel<<<320, 256>>>(W_s2e, W_t2e, W_e2e, W_e2t, W_t2t);

    proj_src_kernel<<<(Bn * NSn) / 64, 256, SM_SINGLE>>>(src);
    proj_tgt_dual_kernel<<<(Bn * NTn) / 64, 256, SM_DUAL>>>(tgt);

    cudaMemcpyAsync(out1, src, (size_t)Bn * NSn * D * sizeof(float),
                    cudaMemcpyDeviceToDevice, 0);

    bond_kernel<<<nsm, 256, SM_BOND>>>(bond, ln1_g, ln1_b, so, to, out0);

    reduce_kernel<<<(Bn * NTn) / 8, 256>>>(eo, coef);

    tgt_kernel<<<(Bn * NTn) / 64, 256, SM_SINGLE>>>(tgt, ln2_g, ln2_b, out2);
}